// round 8
// baseline (speedup 1.0000x reference)
#include <cuda_runtime.h>
#include <cuda_bf16.h>
#include <cstddef>

// Problem constants
#define T_STEPS 256
#define B_SZ    64
#define K_DIM   1024
#define H_DIM   1024
#define L_NUM   3
#define THREE_H 3072
#define M_ROWS  16384
#define NBLK    128

typedef unsigned long long ull;

// ---------------------------------------------------------------------------
// Scratch (device globals — allocation-free per harness rules)
// ---------------------------------------------------------------------------
__device__ float g_gi [(size_t)M_ROWS * THREE_H];   // [T*B, 3H] gate-interleaved
__device__ float g_seq[(size_t)M_ROWS * H_DIM];     // [T, B, H] layer output
__device__ float g_hp [2][(size_t)H_DIM * B_SZ];    // ping-pong h, plain [k][b]
__device__ unsigned g_bar_cnt = 0;
__device__ unsigned g_bar_gen = 0;

// ---------------------------------------------------------------------------
// f32x2 helpers
// ---------------------------------------------------------------------------
__device__ __forceinline__ void fma2(ull& d, ull a, ull b) {
    asm("fma.rn.f32x2 %0, %1, %2, %0;" : "+l"(d) : "l"(a), "l"(b));
}
__device__ __forceinline__ ull add2(ull a, ull b) {
    ull r;
    asm("add.rn.f32x2 %0, %1, %2;" : "=l"(r) : "l"(a), "l"(b));
    return r;
}
__device__ __forceinline__ ull dup2(float x) {
    ull r;
    unsigned u = __float_as_uint(x);
    asm("mov.b64 %0, {%1,%1};" : "=l"(r) : "r"(u));
    return r;
}
__device__ __forceinline__ void cp16(void* dst, const void* src) {
    unsigned sa = (unsigned)__cvta_generic_to_shared(dst);
    asm volatile("cp.async.cg.shared.global [%0], [%1], 16;" :: "r"(sa), "l"(src));
}
__device__ __forceinline__ void cp_commit() {
    asm volatile("cp.async.commit_group;" ::: "memory");
}
template <int N>
__device__ __forceinline__ void cp_wait() {
    asm volatile("cp.async.wait_group %0;" :: "n"(N) : "memory");
}
__device__ __forceinline__ float sigm(float x) { return 1.0f / (1.0f + expf(-x)); }

// ---------------------------------------------------------------------------
// Kernel 1: gi = A @ Wih^T + b_ih (cols gate-interleaved c = j*3+gate).
// f32x2: lanes = adjacent output-column pairs. (unchanged)
// ---------------------------------------------------------------------------
#define BM 128
#define BN 128
#define BK 16
#define NIT (K_DIM / BK)    // 64

__global__ __launch_bounds__(256, 2) void gi_gemm_kernel(
    const float* __restrict__ A, const float* __restrict__ W,
    const float* __restrict__ bias, float* __restrict__ out)
{
    __shared__ float2 As[2][BK * 128];   // [k][m] duplicated (a,a)
    __shared__ float  Bs[2][BK * 128];   // [k][n] plain

    const int tid = threadIdx.x;
    const int tx  = tid & 15;
    const int ty  = tid >> 4;
    const int bm  = blockIdx.y * BM;
    const int bn  = blockIdx.x * BN;

    const int sm_ = tid >> 1;
    const int sk8 = (tid & 1) * 8;
    const float* aptr = A + (size_t)(bm + sm_) * K_DIM + sk8;
    const int    cB   = bn + sm_;
    const float* bptr = W + (size_t)((cB % 3) * H_DIM + cB / 3) * K_DIM + sk8;

    ull biasp[4];
    #pragma unroll
    for (int p = 0; p < 4; p++) {
        int c0 = bn + tx * 8 + 2 * p;
        float blo = bias[(c0 % 3) * H_DIM + c0 / 3];
        float bhi = bias[((c0 + 1) % 3) * H_DIM + (c0 + 1) / 3];
        float2 bp = make_float2(blo, bhi);
        biasp[p] = *(ull*)&bp;
    }

    ull acc[8][4];
    #pragma unroll
    for (int m = 0; m < 8; m++)
        #pragma unroll
        for (int p = 0; p < 4; p++)
            acc[m][p] = 0ull;

    float4 ra0 = *(const float4*)(aptr);
    float4 ra1 = *(const float4*)(aptr + 4);
    float4 rb0 = *(const float4*)(bptr);
    float4 rb1 = *(const float4*)(bptr + 4);
    {
        float a[8] = {ra0.x, ra0.y, ra0.z, ra0.w, ra1.x, ra1.y, ra1.z, ra1.w};
        float b[8] = {rb0.x, rb0.y, rb0.z, rb0.w, rb1.x, rb1.y, rb1.z, rb1.w};
        #pragma unroll
        for (int j = 0; j < 8; j++) {
            As[0][(sk8 + j) * 128 + sm_] = make_float2(a[j], a[j]);
            Bs[0][(sk8 + j) * 128 + sm_] = b[j];
        }
    }
    __syncthreads();

    for (int it = 0; it < NIT; it++) {
        const int cur = it & 1;
        if (it + 1 < NIT) {
            const float* ap = aptr + (it + 1) * BK;
            const float* bp = bptr + (it + 1) * BK;
            ra0 = *(const float4*)(ap);
            ra1 = *(const float4*)(ap + 4);
            rb0 = *(const float4*)(bp);
            rb1 = *(const float4*)(bp + 4);
        }
        #pragma unroll
        for (int k = 0; k < BK; k++) {
            const ulonglong2* ar = (const ulonglong2*)&As[cur][k * 128 + ty * 8];
            const ulonglong2* br = (const ulonglong2*)&Bs[cur][k * 128 + tx * 8];
            ulonglong2 a01 = ar[0], a23 = ar[1], a45 = ar[2], a67 = ar[3];
            ulonglong2 b01 = br[0], b23 = br[1];
            ull av[8] = {a01.x, a01.y, a23.x, a23.y, a45.x, a45.y, a67.x, a67.y};
            ull bv[4] = {b01.x, b01.y, b23.x, b23.y};
            #pragma unroll
            for (int m = 0; m < 8; m++)
                #pragma unroll
                for (int p = 0; p < 4; p++)
                    fma2(acc[m][p], av[m], bv[p]);
        }
        if (it + 1 < NIT) {
            const int nxt = cur ^ 1;
            float a[8] = {ra0.x, ra0.y, ra0.z, ra0.w, ra1.x, ra1.y, ra1.z, ra1.w};
            float b[8] = {rb0.x, rb0.y, rb0.z, rb0.w, rb1.x, rb1.y, rb1.z, rb1.w};
            #pragma unroll
            for (int j = 0; j < 8; j++) {
                As[nxt][(sk8 + j) * 128 + sm_] = make_float2(a[j], a[j]);
                Bs[nxt][(sk8 + j) * 128 + sm_] = b[j];
            }
        }
        __syncthreads();
    }

    #pragma unroll
    for (int m = 0; m < 8; m++) {
        float* orow = out + (size_t)(bm + ty * 8 + m) * THREE_H + bn + tx * 8;
        #pragma unroll
        for (int p = 0; p < 4; p++)
            ((ull*)orow)[p] = add2(acc[m][p], biasp[p]);
    }
}

// ---------------------------------------------------------------------------
// h_init: h[k][b] = h0l[b][k]
// ---------------------------------------------------------------------------
__global__ __launch_bounds__(256) void h_init_kernel(
    const float* __restrict__ h0l, float* __restrict__ hdst)
{
    int i = blockIdx.x * 256 + threadIdx.x;
    int k = i >> 6, b = i & 63;
    hdst[i] = h0l[b * H_DIM + k];
}

// ---------------------------------------------------------------------------
// Persistent GRU recurrence — warp-autonomous pipeline.
//  - Warp w owns k rows [w*32, w*32+32) of each 256-k chunk, stages its own
//    8KB via per-thread cp.async groups into warp-private smem (no block
//    syncs in the main loop).
//  - wsm layout (FIXED): per-16-row block stride 386 floats, odd blocks +2:
//      addr(k,c) = (k>>4)*386 + (k&15)*24 + ((k>>4)&1)*2 + c
//    -> no inter-block overlap, halves bank-shifted by 4 (conflict-free).
//  - h rows 16..31 of each warp region offset +4 floats (kills 4-way bank
//    conflict on h LDS.128).
//  - Thread tile 16b (8 f32x2 pairs) x 6 cols; 48 FFMA2/k.
//  - gi/h_prev epilogue operands prefetched at step start.
// ---------------------------------------------------------------------------
#define WBLK_STRIDE 386                    // 16*24 + 2
#define WSM_FLOATS  (64 * WBLK_STRIDE)     // 24704
#define WREG        2056                   // 32*64 + 4 offset + 4 pad
#define HBUF_FLOATS (8 * WREG)             // 16448
#define RDYN_BYTES  ((WSM_FLOATS + 2 * HBUF_FLOATS) * 4)   // 230400

__device__ __forceinline__ void grid_sync_() {
    __threadfence();
    __syncthreads();
    if (threadIdx.x == 0) {
        unsigned gen = *(volatile unsigned*)&g_bar_gen;
        unsigned ticket = atomicAdd(&g_bar_cnt, 1u);
        if (ticket == NBLK - 1) {
            g_bar_cnt = 0;
            __threadfence();
            atomicAdd(&g_bar_gen, 1u);
        } else {
            while (*(volatile unsigned*)&g_bar_gen == gen) __nanosleep(20);
        }
    }
    __syncthreads();
}

__global__ __launch_bounds__(256, 1) void gru_persistent_kernel(
    const float* __restrict__ gi,     // [T, B, 3H] interleaved
    float* __restrict__ h,            // [2][1024][64] plain
    const float* __restrict__ whh,    // [3H, H]
    const float* __restrict__ bhh,    // [3H]
    float* __restrict__ seq_out,      // [T, B, H] or nullptr
    float* __restrict__ hlast)        // [B, H]
{
    extern __shared__ float dyn[];
    float* wsm  = dyn;                 // blocked layout, see header
    float* hbuf = dyn + WSM_FLOATS;    // [2][8 warps][WREG]

    const int tid   = threadIdx.x;
    const int jbase = blockIdx.x * 8;
    const int w     = tid >> 5;        // warp 0..7
    const int lane  = tid & 31;
    const int half  = lane >> 4;       // k-half within warp's 32 rows
    const int l16   = lane & 15;
    const int bbase = (l16 >> 2) * 16; // 16 b rows (8 pairs)
    const int cbase = (l16 & 3) * 6;   // 6 cols

    // Load Whh slice into blocked layout
    for (int idx = tid; idx < 24576; idx += 256) {
        int c = idx >> 10, k = idx & 1023;
        int kb = k >> 4;
        int addr = kb * WBLK_STRIDE + (k & 15) * 24 + (kb & 1) * 2 + c;
        int row = (c % 3) * H_DIM + (jbase + c / 3);
        wsm[addr] = whh[(size_t)row * H_DIM + k];
    }
    const int ep_j  = tid & 7;
    const int ep_jg = jbase + ep_j;
    const float br  = bhh[ep_jg];
    const float bz  = bhh[H_DIM + ep_jg];
    const float bn_ = bhh[2 * H_DIM + ep_jg];
    const int ep_b0 = tid >> 3;
    const int ep_b1 = (tid + 256) >> 3;
    __syncthreads();

    const bool wr_seq = (seq_out != nullptr);

    // warp-private smem base offsets
    float* wreg0 = hbuf + w * WREG;                 // buf 0
    float* wreg1 = hbuf + HBUF_FLOATS + w * WREG;   // buf 1
    // compute-side row base for this thread's half
    const int half_off = half * (16 * 64 + 4);

    for (int t = 0; t < T_STEPS; t++) {
        const float* hin  = h + (size_t)(t & 1) * (H_DIM * B_SZ);
        float*       hout = h + (size_t)((t + 1) & 1) * (H_DIM * B_SZ);
        const float* gi_t = gi + (size_t)t * B_SZ * THREE_H;

        grid_sync_();   // prev-step h visible; smem overlays free

        // ---- stage chunk 0 (warp-private) ----
        {
            const float* src = hin + (0 * 256 + w * 32) * 64;
            #pragma unroll
            for (int i = 0; i < 16; i++) {
                int idx = i * 32 + lane;
                int row = idx >> 4;
                int col = (idx & 15) * 4;
                cp16(wreg0 + row * 64 + ((row >> 4) & 1) * 4 + col,
                     src + idx * 4);
            }
            cp_commit();
        }

        // ---- prefetch epilogue operands (overlap with compute) ----
        float g0a = __ldg(gi_t + (size_t)ep_b0 * THREE_H + ep_jg * 3 + 0);
        float g0b = __ldg(gi_t + (size_t)ep_b0 * THREE_H + ep_jg * 3 + 1);
        float g0c = __ldg(gi_t + (size_t)ep_b0 * THREE_H + ep_jg * 3 + 2);
        float g1a = __ldg(gi_t + (size_t)ep_b1 * THREE_H + ep_jg * 3 + 0);
        float g1b = __ldg(gi_t + (size_t)ep_b1 * THREE_H + ep_jg * 3 + 1);
        float g1c = __ldg(gi_t + (size_t)ep_b1 * THREE_H + ep_jg * 3 + 2);
        float hp0 = __ldcg(hin + ep_jg * 64 + ep_b0);
        float hp1 = __ldcg(hin + ep_jg * 64 + ep_b1);

        ull acc[8][6];
        #pragma unroll
        for (int p = 0; p < 8; p++)
            #pragma unroll
            for (int c = 0; c < 6; c++)
                acc[p][c] = 0ull;

        // ---- warp-autonomous chunk loop (no block syncs) ----
        #pragma unroll 1
        for (int ch = 0; ch < 4; ch++) {
            if (ch < 3) {
                float* dst = (ch & 1) ? wreg0 : wreg1;   // buf (ch+1)&1
                const float* src = hin + ((ch + 1) * 256 + w * 32) * 64;
                #pragma unroll
                for (int i = 0; i < 16; i++) {
                    int idx = i * 32 + lane;
                    int row = idx >> 4;
                    int col = (idx & 15) * 4;
                    cp16(dst + row * 64 + ((row >> 4) & 1) * 4 + col,
                         src + idx * 4);
                }
                cp_commit();
                cp_wait<1>();
            } else {
                cp_wait<0>();
            }
            __syncwarp();

            const float* hrow = ((ch & 1) ? wreg1 : wreg0) + half_off + bbase;
            // k block index for this warp/half/chunk: kb = ch*16 + w*2 + half
            const int kb  = ch * 16 + w * 2 + half;
            const float* wr_ = wsm + kb * WBLK_STRIDE + half * 2 + cbase;
            #pragma unroll 8
            for (int r = 0; r < 16; r++) {
                const float* wp = wr_ + r * 24;
                float2 w01 = *(const float2*)(wp);
                float2 w23 = *(const float2*)(wp + 2);
                float2 w45 = *(const float2*)(wp + 4);
                ull wd0 = dup2(w01.x), wd1 = dup2(w01.y);
                ull wd2 = dup2(w23.x), wd3 = dup2(w23.y);
                ull wd4 = dup2(w45.x), wd5 = dup2(w45.y);
                const ulonglong2* hp_ = (const ulonglong2*)(hrow + r * 64);
                ulonglong2 h01 = hp_[0], h23 = hp_[1];
                ulonglong2 h45 = hp_[2], h67 = hp_[3];
                ull hv[8] = {h01.x, h01.y, h23.x, h23.y,
                             h45.x, h45.y, h67.x, h67.y};
                #pragma unroll
                for (int p = 0; p < 8; p++) {
                    fma2(acc[p][0], hv[p], wd0);
                    fma2(acc[p][1], hv[p], wd1);
                    fma2(acc[p][2], hv[p], wd2);
                    fma2(acc[p][3], hv[p], wd3);
                    fma2(acc[p][4], hv[p], wd4);
                    fma2(acc[p][5], hv[p], wd5);
                }
            }
        }

        // ---- partials to smem (overlay on h buffers) ----
        __syncthreads();    // all warps done with their buffers
        ull* red = (ull*)(dyn + WSM_FLOATS);   // [16 g][16 lt][48]
        {
            const int g16 = w * 2 + half;
            ull* mine = red + (g16 * 16 + l16) * 48;
            #pragma unroll
            for (int p = 0; p < 8; p++)
                #pragma unroll
                for (int c = 0; c < 6; c++)
                    mine[p * 6 + c] = acc[p][c];
        }
        __syncthreads();

        // ---- gate epilogue: 512 (b,j) units, 2 per thread ----
        #pragma unroll
        for (int uu = 0; uu < 2; uu++) {
            int b  = uu ? ep_b1 : ep_b0;
            int bq = b >> 4;
            int p_ = (b & 15) >> 1;
            int ln = b & 1;
            float s[3];
            #pragma unroll
            for (int gt = 0; gt < 3; gt++) {
                int cg  = ep_j * 3 + gt;
                int ltp = bq * 4 + cg / 6;
                int idx = p_ * 6 + (cg % 6);
                float acc_s = 0.f;
                #pragma unroll
                for (int gg = 0; gg < 16; gg++) {
                    ull v = red[(gg * 16 + ltp) * 48 + idx];
                    float2 f = *(float2*)&v;
                    acc_s += ln ? f.y : f.x;
                }
                s[gt] = acc_s;
            }
            float ga = uu ? g1a : g0a;
            float gb = uu ? g1b : g0b;
            float gc = uu ? g1c : g0c;
            float hp = uu ? hp1 : hp0;
            float r  = sigm(ga + s[0] + br);
            float z  = sigm(gb + s[1] + bz);
            float n  = tanhf(gc + r * (s[2] + bn_));
            float hn = (1.0f - z) * n + z * hp;
            hout[ep_jg * 64 + b] = hn;
            if (wr_seq)
                seq_out[(size_t)t * (B_SZ * H_DIM) + (size_t)b * H_DIM + ep_jg] = hn;
            if (t == T_STEPS - 1)
                hlast[(size_t)b * H_DIM + ep_jg] = hn;
        }
    }
}

// ---------------------------------------------------------------------------
// Launch
// ---------------------------------------------------------------------------
extern "C" void kernel_launch(void* const* d_in, const int* in_sizes, int n_in,
                              void* d_out, int out_size)
{
    (void)in_sizes; (void)n_in; (void)out_size;

    const float* x    = (const float*)d_in[0];
    const float* h0   = (const float*)d_in[1];
    const float* w_ih = (const float*)d_in[2];
    const float* w_hh = (const float*)d_in[3];
    const float* b_ih = (const float*)d_in[4];
    const float* b_hh = (const float*)d_in[5];
    float* out = (float*)d_out;

    float* gi  = nullptr;
    float* seq = nullptr;
    float* hp  = nullptr;
    cudaGetSymbolAddress((void**)&gi,  g_gi);
    cudaGetSymbolAddress((void**)&seq, g_seq);
    cudaGetSymbolAddress((void**)&hp,  g_hp);

    cudaFuncSetAttribute(gru_persistent_kernel,
                         cudaFuncAttributeMaxDynamicSharedMemorySize,
                         RDYN_BYTES);

    const size_t BH = (size_t)B_SZ * H_DIM;   // 65536
    dim3 ggrid(THREE_H / BN, M_ROWS / BM);    // (24, 128)

    for (int l = 0; l < L_NUM; l++) {
        const float* A = (l == 0) ? x : seq;
        gi_gemm_kernel<<<ggrid, 256>>>(A,
                                       w_ih + (size_t)l * THREE_H * K_DIM,
                                       b_ih + (size_t)l * THREE_H,
                                       gi);
        h_init_kernel<<<256, 256>>>(h0 + (size_t)l * BH, hp);
        gru_persistent_kernel<<<NBLK, 256, RDYN_BYTES>>>(
            gi, hp,
            w_hh + (size_t)l * THREE_H * H_DIM,
            b_hh + (size_t)l * THREE_H,
            (l < L_NUM - 1) ? seq : nullptr,
            out + (size_t)l * BH);
    }
}

// round 9
// speedup vs baseline: 1.1194x; 1.1194x over previous
#include <cuda_runtime.h>
#include <cuda_bf16.h>
#include <cstddef>

// Problem constants
#define T_STEPS 256
#define B_SZ    64
#define K_DIM   1024
#define H_DIM   1024
#define L_NUM   3
#define THREE_H 3072
#define M_ROWS  16384
#define NBLK    128

typedef unsigned long long ull;

// ---------------------------------------------------------------------------
// Scratch (device globals — allocation-free per harness rules)
// ---------------------------------------------------------------------------
__device__ float g_gi [(size_t)M_ROWS * THREE_H];   // [T*B, 3H] gate-interleaved
__device__ float g_seq[(size_t)M_ROWS * H_DIM];     // [T, B, H] layer output
__device__ float g_hp [2][(size_t)H_DIM * B_SZ];    // ping-pong h, plain [k][b]
__device__ unsigned g_bar_cnt = 0;
__device__ unsigned g_bar_gen = 0;

// ---------------------------------------------------------------------------
// f32x2 helpers
// ---------------------------------------------------------------------------
__device__ __forceinline__ void fma2(ull& d, ull a, ull b) {
    asm("fma.rn.f32x2 %0, %1, %2, %0;" : "+l"(d) : "l"(a), "l"(b));
}
__device__ __forceinline__ ull add2(ull a, ull b) {
    ull r;
    asm("add.rn.f32x2 %0, %1, %2;" : "=l"(r) : "l"(a), "l"(b));
    return r;
}
__device__ __forceinline__ ull dup2(float x) {
    ull r;
    unsigned u = __float_as_uint(x);
    asm("mov.b64 %0, {%1,%1};" : "=l"(r) : "r"(u));
    return r;
}
__device__ __forceinline__ void cp16(void* dst, const void* src) {
    unsigned sa = (unsigned)__cvta_generic_to_shared(dst);
    asm volatile("cp.async.cg.shared.global [%0], [%1], 16;" :: "r"(sa), "l"(src));
}
__device__ __forceinline__ void cp_commit() {
    asm volatile("cp.async.commit_group;" ::: "memory");
}
template <int N>
__device__ __forceinline__ void cp_wait() {
    asm volatile("cp.async.wait_group %0;" :: "n"(N) : "memory");
}
__device__ __forceinline__ float sigm(float x) { return 1.0f / (1.0f + expf(-x)); }

// ---------------------------------------------------------------------------
// Kernel 1: gi = A @ Wih^T + b_ih (cols gate-interleaved c = j*3+gate).
// f32x2: lanes = adjacent output-column pairs. (unchanged)
// ---------------------------------------------------------------------------
#define BM 128
#define BN 128
#define BK 16
#define NIT (K_DIM / BK)    // 64

__global__ __launch_bounds__(256, 2) void gi_gemm_kernel(
    const float* __restrict__ A, const float* __restrict__ W,
    const float* __restrict__ bias, float* __restrict__ out)
{
    __shared__ float2 As[2][BK * 128];   // [k][m] duplicated (a,a)
    __shared__ float  Bs[2][BK * 128];   // [k][n] plain

    const int tid = threadIdx.x;
    const int tx  = tid & 15;
    const int ty  = tid >> 4;
    const int bm  = blockIdx.y * BM;
    const int bn  = blockIdx.x * BN;

    const int sm_ = tid >> 1;
    const int sk8 = (tid & 1) * 8;
    const float* aptr = A + (size_t)(bm + sm_) * K_DIM + sk8;
    const int    cB   = bn + sm_;
    const float* bptr = W + (size_t)((cB % 3) * H_DIM + cB / 3) * K_DIM + sk8;

    ull biasp[4];
    #pragma unroll
    for (int p = 0; p < 4; p++) {
        int c0 = bn + tx * 8 + 2 * p;
        float blo = bias[(c0 % 3) * H_DIM + c0 / 3];
        float bhi = bias[((c0 + 1) % 3) * H_DIM + (c0 + 1) / 3];
        float2 bp = make_float2(blo, bhi);
        biasp[p] = *(ull*)&bp;
    }

    ull acc[8][4];
    #pragma unroll
    for (int m = 0; m < 8; m++)
        #pragma unroll
        for (int p = 0; p < 4; p++)
            acc[m][p] = 0ull;

    float4 ra0 = *(const float4*)(aptr);
    float4 ra1 = *(const float4*)(aptr + 4);
    float4 rb0 = *(const float4*)(bptr);
    float4 rb1 = *(const float4*)(bptr + 4);
    {
        float a[8] = {ra0.x, ra0.y, ra0.z, ra0.w, ra1.x, ra1.y, ra1.z, ra1.w};
        float b[8] = {rb0.x, rb0.y, rb0.z, rb0.w, rb1.x, rb1.y, rb1.z, rb1.w};
        #pragma unroll
        for (int j = 0; j < 8; j++) {
            As[0][(sk8 + j) * 128 + sm_] = make_float2(a[j], a[j]);
            Bs[0][(sk8 + j) * 128 + sm_] = b[j];
        }
    }
    __syncthreads();

    for (int it = 0; it < NIT; it++) {
        const int cur = it & 1;
        if (it + 1 < NIT) {
            const float* ap = aptr + (it + 1) * BK;
            const float* bp = bptr + (it + 1) * BK;
            ra0 = *(const float4*)(ap);
            ra1 = *(const float4*)(ap + 4);
            rb0 = *(const float4*)(bp);
            rb1 = *(const float4*)(bp + 4);
        }
        #pragma unroll
        for (int k = 0; k < BK; k++) {
            const ulonglong2* ar = (const ulonglong2*)&As[cur][k * 128 + ty * 8];
            const ulonglong2* br = (const ulonglong2*)&Bs[cur][k * 128 + tx * 8];
            ulonglong2 a01 = ar[0], a23 = ar[1], a45 = ar[2], a67 = ar[3];
            ulonglong2 b01 = br[0], b23 = br[1];
            ull av[8] = {a01.x, a01.y, a23.x, a23.y, a45.x, a45.y, a67.x, a67.y};
            ull bv[4] = {b01.x, b01.y, b23.x, b23.y};
            #pragma unroll
            for (int m = 0; m < 8; m++)
                #pragma unroll
                for (int p = 0; p < 4; p++)
                    fma2(acc[m][p], av[m], bv[p]);
        }
        if (it + 1 < NIT) {
            const int nxt = cur ^ 1;
            float a[8] = {ra0.x, ra0.y, ra0.z, ra0.w, ra1.x, ra1.y, ra1.z, ra1.w};
            float b[8] = {rb0.x, rb0.y, rb0.z, rb0.w, rb1.x, rb1.y, rb1.z, rb1.w};
            #pragma unroll
            for (int j = 0; j < 8; j++) {
                As[nxt][(sk8 + j) * 128 + sm_] = make_float2(a[j], a[j]);
                Bs[nxt][(sk8 + j) * 128 + sm_] = b[j];
            }
        }
        __syncthreads();
    }

    #pragma unroll
    for (int m = 0; m < 8; m++) {
        float* orow = out + (size_t)(bm + ty * 8 + m) * THREE_H + bn + tx * 8;
        #pragma unroll
        for (int p = 0; p < 4; p++)
            ((ull*)orow)[p] = add2(acc[m][p], biasp[p]);
    }
}

// ---------------------------------------------------------------------------
// h_init: h[k][b] = h0l[b][k]
// ---------------------------------------------------------------------------
__global__ __launch_bounds__(256) void h_init_kernel(
    const float* __restrict__ h0l, float* __restrict__ hdst)
{
    int i = blockIdx.x * 256 + threadIdx.x;
    int k = i >> 6, b = i & 63;
    hdst[i] = h0l[b * H_DIM + k];
}

// ---------------------------------------------------------------------------
// Persistent GRU recurrence — 512 threads, conflict-free smem.
//  - 16 warps; warp w owns k-slab [w*8, w*8+8) of each 128-k chunk.
//  - Lane tile 8b x 6c (bgrp = lane>>2, cgrp = lane&3): 24 FFMA2/k, 24 acc ull.
//  - h smem row stride 68, +4 pad after bgrp 3: the 8 bgrp LDS.128 addresses
//    cover all 32 banks (conflict-free, both 16B fragments).
//  - wsm plain [k][24]: all lanes share k -> w LDS.64 addrs {c, c+6, c+12,
//    c+18} bank-disjoint.
//  - 8 chunks of 128 k, 32KB each, cp.async double-buffered.
//  - 2-stage cross-warp reduction (warps 8-15 -> 0-7 -> 512-thread epilogue).
// ---------------------------------------------------------------------------
#define NTHR        512
#define WSM_FLOATS  24576                  // 1024 * 24
#define HROW        68                     // 64 + 4 pad
#define HBUF_FLOATS (128 * HROW)           // 8704
#define RDYN_BYTES  ((WSM_FLOATS + 2 * HBUF_FLOATS) * 4)   // 167936

__device__ __forceinline__ void grid_sync_() {
    __threadfence();
    __syncthreads();
    if (threadIdx.x == 0) {
        unsigned gen = *(volatile unsigned*)&g_bar_gen;
        unsigned ticket = atomicAdd(&g_bar_cnt, 1u);
        if (ticket == NBLK - 1) {
            g_bar_cnt = 0;
            __threadfence();
            atomicAdd(&g_bar_gen, 1u);
        } else {
            while (*(volatile unsigned*)&g_bar_gen == gen) __nanosleep(20);
        }
    }
    __syncthreads();
}

__global__ __launch_bounds__(NTHR, 1) void gru_persistent_kernel(
    const float* __restrict__ gi,     // [T, B, 3H] interleaved
    float* __restrict__ h,            // [2][1024][64] plain
    const float* __restrict__ whh,    // [3H, H]
    const float* __restrict__ bhh,    // [3H]
    float* __restrict__ seq_out,      // [T, B, H] or nullptr
    float* __restrict__ hlast)        // [B, H]
{
    extern __shared__ float dyn[];
    float* wsm  = dyn;                 // [1024][24]
    float* hbuf = dyn + WSM_FLOATS;    // [2][128 rows][68]

    const int tid   = threadIdx.x;
    const int jbase = blockIdx.x * 8;
    const int w     = tid >> 5;        // warp 0..15 (owns k-slab w*8..w*8+7)
    const int lane  = tid & 31;
    const int bgrp  = lane >> 2;       // 0..7: b in [bgrp*8, bgrp*8+8)
    const int cgrp  = lane & 3;        // 0..3: c in [cgrp*6, cgrp*6+6)
    const int cbase = cgrp * 6;
    const int hoff  = bgrp * 8 + ((bgrp >> 2) << 2);   // padded bgrp offset

    // Load Whh slice (plain [k][24])
    for (int idx = tid; idx < WSM_FLOATS; idx += NTHR) {
        int c = idx >> 10, k = idx & 1023;
        int row = (c % 3) * H_DIM + (jbase + c / 3);
        wsm[k * 24 + c] = whh[(size_t)row * H_DIM + k];
    }
    // Epilogue: 1 (b, j) unit per thread
    const int ep_j  = tid & 7;
    const int ep_b  = tid >> 3;        // 0..63
    const int ep_jg = jbase + ep_j;
    const float br  = bhh[ep_jg];
    const float bz  = bhh[H_DIM + ep_jg];
    const float bn_ = bhh[2 * H_DIM + ep_jg];
    __syncthreads();

    const bool wr_seq = (seq_out != nullptr);

    for (int t = 0; t < T_STEPS; t++) {
        const float* hin  = h + (size_t)(t & 1) * (H_DIM * B_SZ);
        float*       hout = h + (size_t)((t + 1) & 1) * (H_DIM * B_SZ);
        const float* gi_t = gi + (size_t)t * B_SZ * THREE_H;

        grid_sync_();   // prev-step h visible; smem overlays free

        // ---- stage chunk 0 ----
        {
            #pragma unroll
            for (int i = 0; i < 4; i++) {
                int idx = i * NTHR + tid;        // 0..2047
                int row = idx >> 4;
                int q   = idx & 15;
                cp16(hbuf + row * HROW + q * 4 + ((q >> 3) << 2),
                     hin + row * 64 + q * 4);
            }
            cp_commit();
        }

        // ---- prefetch epilogue operands ----
        float ga = __ldg(gi_t + (size_t)ep_b * THREE_H + ep_jg * 3 + 0);
        float gb = __ldg(gi_t + (size_t)ep_b * THREE_H + ep_jg * 3 + 1);
        float gc = __ldg(gi_t + (size_t)ep_b * THREE_H + ep_jg * 3 + 2);
        float hp = __ldcg(hin + ep_jg * 64 + ep_b);

        ull acc[4][6];
        #pragma unroll
        for (int p = 0; p < 4; p++)
            #pragma unroll
            for (int c = 0; c < 6; c++)
                acc[p][c] = 0ull;

        // ---- chunk loop: 8 chunks of 128 k, double-buffered ----
        #pragma unroll 1
        for (int ch = 0; ch < 8; ch++) {
            if (ch < 7) {
                float* dst = hbuf + ((ch + 1) & 1) * HBUF_FLOATS;
                const float* src = hin + (ch + 1) * 128 * 64;
                #pragma unroll
                for (int i = 0; i < 4; i++) {
                    int idx = i * NTHR + tid;
                    int row = idx >> 4;
                    int q   = idx & 15;
                    cp16(dst + row * HROW + q * 4 + ((q >> 3) << 2),
                         src + row * 64 + q * 4);
                }
                cp_commit();
                cp_wait<1>();
            } else {
                cp_wait<0>();
            }
            __syncthreads();

            const float* hb  = hbuf + (ch & 1) * HBUF_FLOATS;
            const float* wr_ = wsm + (ch * 128 + w * 8) * 24 + cbase;
            const float* hr  = hb + (w * 8) * HROW + hoff;
            #pragma unroll
            for (int r = 0; r < 8; r++) {
                const float* wp = wr_ + r * 24;
                float2 w01 = *(const float2*)(wp);
                float2 w23 = *(const float2*)(wp + 2);
                float2 w45 = *(const float2*)(wp + 4);
                ull wd0 = dup2(w01.x), wd1 = dup2(w01.y);
                ull wd2 = dup2(w23.x), wd3 = dup2(w23.y);
                ull wd4 = dup2(w45.x), wd5 = dup2(w45.y);
                const ulonglong2* hp_ = (const ulonglong2*)(hr + r * HROW);
                ulonglong2 h01 = hp_[0], h23 = hp_[1];
                ull hv[4] = {h01.x, h01.y, h23.x, h23.y};
                #pragma unroll
                for (int p = 0; p < 4; p++) {
                    fma2(acc[p][0], hv[p], wd0);
                    fma2(acc[p][1], hv[p], wd1);
                    fma2(acc[p][2], hv[p], wd2);
                    fma2(acc[p][3], hv[p], wd3);
                    fma2(acc[p][4], hv[p], wd4);
                    fma2(acc[p][5], hv[p], wd5);
                }
            }
            __syncthreads();
        }

        // ---- 2-stage cross-warp reduction (overlay on h buffers) ----
        ull* red = (ull*)(dyn + WSM_FLOATS);   // [8][32][24] ull = 48KB
        if (w >= 8) {
            ull* mine = red + ((w - 8) * 32 + lane) * 24;
            #pragma unroll
            for (int p = 0; p < 4; p++)
                #pragma unroll
                for (int c = 0; c < 6; c++)
                    mine[p * 6 + c] = acc[p][c];
        }
        __syncthreads();
        if (w < 8) {
            ull* mine = red + (w * 32 + lane) * 24;
            #pragma unroll
            for (int p = 0; p < 4; p++)
                #pragma unroll
                for (int c = 0; c < 6; c++) {
                    acc[p][c] = add2(acc[p][c], mine[p * 6 + c]);
                    mine[p * 6 + c] = acc[p][c];
                }
        }
        __syncthreads();

        // ---- gate epilogue: 1 (b, j) unit per thread ----
        {
            const int b  = ep_b;
            const int hf = b & 1;
            float s[3];
            #pragma unroll
            for (int gt = 0; gt < 3; gt++) {
                int cg   = ep_j * 3 + gt;            // 0..23
                int cgr  = cg / 6;
                int slot = (((b >> 1) & 3)) * 6 + (cg % 6);
                int lnr  = (b >> 3) * 4 + cgr;
                float acc_s = 0.f;
                #pragma unroll
                for (int u = 0; u < 8; u++) {
                    ull v = red[(u * 32 + lnr) * 24 + slot];
                    float2 f = *(float2*)&v;
                    acc_s += hf ? f.y : f.x;
                }
                s[gt] = acc_s;
            }
            float r  = sigm(ga + s[0] + br);
            float z  = sigm(gb + s[1] + bz);
            float n  = tanhf(gc + r * (s[2] + bn_));
            float hn = (1.0f - z) * n + z * hp;
            hout[ep_jg * 64 + b] = hn;
            if (wr_seq)
                seq_out[(size_t)t * (B_SZ * H_DIM) + (size_t)b * H_DIM + ep_jg] = hn;
            if (t == T_STEPS - 1)
                hlast[(size_t)b * H_DIM + ep_jg] = hn;
        }
    }
}

// ---------------------------------------------------------------------------
// Launch
// ---------------------------------------------------------------------------
extern "C" void kernel_launch(void* const* d_in, const int* in_sizes, int n_in,
                              void* d_out, int out_size)
{
    (void)in_sizes; (void)n_in; (void)out_size;

    const float* x    = (const float*)d_in[0];
    const float* h0   = (const float*)d_in[1];
    const float* w_ih = (const float*)d_in[2];
    const float* w_hh = (const float*)d_in[3];
    const float* b_ih = (const float*)d_in[4];
    const float* b_hh = (const float*)d_in[5];
    float* out = (float*)d_out;

    float* gi  = nullptr;
    float* seq = nullptr;
    float* hp  = nullptr;
    cudaGetSymbolAddress((void**)&gi,  g_gi);
    cudaGetSymbolAddress((void**)&seq, g_seq);
    cudaGetSymbolAddress((void**)&hp,  g_hp);

    cudaFuncSetAttribute(gru_persistent_kernel,
                         cudaFuncAttributeMaxDynamicSharedMemorySize,
                         RDYN_BYTES);

    const size_t BH = (size_t)B_SZ * H_DIM;   // 65536
    dim3 ggrid(THREE_H / BN, M_ROWS / BM);    // (24, 128)

    for (int l = 0; l < L_NUM; l++) {
        const float* A = (l == 0) ? x : seq;
        gi_gemm_kernel<<<ggrid, 256>>>(A,
                                       w_ih + (size_t)l * THREE_H * K_DIM,
                                       b_ih + (size_t)l * THREE_H,
                                       gi);
        h_init_kernel<<<256, 256>>>(h0 + (size_t)l * BH, hp);
        gru_persistent_kernel<<<NBLK, NTHR, RDYN_BYTES>>>(
            gi, hp,
            w_hh + (size_t)l * THREE_H * H_DIM,
            b_hh + (size_t)l * THREE_H,
            (l < L_NUM - 1) ? seq : nullptr,
            out + (size_t)l * BH);
    }
}

// round 11
// speedup vs baseline: 1.2128x; 1.0834x over previous
#include <cuda_runtime.h>
#include <cuda_bf16.h>
#include <cstddef>
#include <cstdint>

// Problem constants
#define T_STEPS 256
#define B_SZ    64
#define K_DIM   1024
#define H_DIM   1024
#define L_NUM   3
#define THREE_H 3072
#define M_ROWS  16384
#define NBLK    128
#define NTHR    512

typedef unsigned long long ull;

// ---------------------------------------------------------------------------
// Scratch (device globals — allocation-free per harness rules)
// ---------------------------------------------------------------------------
__device__ float g_gi [(size_t)M_ROWS * THREE_H];   // [T*B, 3H] gate-interleaved
__device__ float g_seq[(size_t)M_ROWS * H_DIM];     // [T, B, H] layer output
__device__ __nv_bfloat16 g_h16hi[2][(size_t)B_SZ * H_DIM];  // ping-pong h hi
__device__ __nv_bfloat16 g_h16lo[2][(size_t)B_SZ * H_DIM];  // ping-pong h lo
__device__ unsigned g_bar_cnt = 0;
__device__ unsigned g_bar_gen = 0;

// ---------------------------------------------------------------------------
// helpers
// ---------------------------------------------------------------------------
__device__ __forceinline__ void fma2(ull& d, ull a, ull b) {
    asm("fma.rn.f32x2 %0, %1, %2, %0;" : "+l"(d) : "l"(a), "l"(b));
}
__device__ __forceinline__ ull add2(ull a, ull b) {
    ull r;
    asm("add.rn.f32x2 %0, %1, %2;" : "=l"(r) : "l"(a), "l"(b));
    return r;
}
__device__ __forceinline__ float sigm(float x) { return 1.0f / (1.0f + expf(-x)); }

// bf16 HMMA: D[16,8] += A[16,16] * B[16,8]  (A row-major frags, B col-major)
__device__ __forceinline__ void mma_bf16(
    float* d, uint32_t a0, uint32_t a1, uint32_t a2, uint32_t a3,
    uint32_t b0, uint32_t b1)
{
    asm volatile(
        "mma.sync.aligned.m16n8k16.row.col.f32.bf16.bf16.f32 "
        "{%0,%1,%2,%3}, {%4,%5,%6,%7}, {%8,%9}, {%0,%1,%2,%3};"
        : "+f"(d[0]), "+f"(d[1]), "+f"(d[2]), "+f"(d[3])
        : "r"(a0), "r"(a1), "r"(a2), "r"(a3), "r"(b0), "r"(b1));
}

// ---------------------------------------------------------------------------
// Kernel 1: gi = A @ Wih^T + b_ih (cols gate-interleaved c = j*3+gate).
// (unchanged from R5 — f32x2, 128x128x16 tiles)
// ---------------------------------------------------------------------------
#define BM 128
#define BN 128
#define BK 16
#define NIT (K_DIM / BK)    // 64

__device__ __forceinline__ void cp16(void* dst, const void* src) {
    unsigned sa = (unsigned)__cvta_generic_to_shared(dst);
    asm volatile("cp.async.cg.shared.global [%0], [%1], 16;" :: "r"(sa), "l"(src));
}

__global__ __launch_bounds__(256, 2) void gi_gemm_kernel(
    const float* __restrict__ A, const float* __restrict__ W,
    const float* __restrict__ bias, float* __restrict__ out)
{
    __shared__ float2 As[2][BK * 128];
    __shared__ float  Bs[2][BK * 128];

    const int tid = threadIdx.x;
    const int tx  = tid & 15;
    const int ty  = tid >> 4;
    const int bm  = blockIdx.y * BM;
    const int bn  = blockIdx.x * BN;

    const int sm_ = tid >> 1;
    const int sk8 = (tid & 1) * 8;
    const float* aptr = A + (size_t)(bm + sm_) * K_DIM + sk8;
    const int    cB   = bn + sm_;
    const float* bptr = W + (size_t)((cB % 3) * H_DIM + cB / 3) * K_DIM + sk8;

    ull biasp[4];
    #pragma unroll
    for (int p = 0; p < 4; p++) {
        int c0 = bn + tx * 8 + 2 * p;
        float blo = bias[(c0 % 3) * H_DIM + c0 / 3];
        float bhi = bias[((c0 + 1) % 3) * H_DIM + (c0 + 1) / 3];
        float2 bp = make_float2(blo, bhi);
        biasp[p] = *(ull*)&bp;
    }

    ull acc[8][4];
    #pragma unroll
    for (int m = 0; m < 8; m++)
        #pragma unroll
        for (int p = 0; p < 4; p++)
            acc[m][p] = 0ull;

    float4 ra0 = *(const float4*)(aptr);
    float4 ra1 = *(const float4*)(aptr + 4);
    float4 rb0 = *(const float4*)(bptr);
    float4 rb1 = *(const float4*)(bptr + 4);
    {
        float a[8] = {ra0.x, ra0.y, ra0.z, ra0.w, ra1.x, ra1.y, ra1.z, ra1.w};
        float b[8] = {rb0.x, rb0.y, rb0.z, rb0.w, rb1.x, rb1.y, rb1.z, rb1.w};
        #pragma unroll
        for (int j = 0; j < 8; j++) {
            As[0][(sk8 + j) * 128 + sm_] = make_float2(a[j], a[j]);
            Bs[0][(sk8 + j) * 128 + sm_] = b[j];
        }
    }
    __syncthreads();

    for (int it = 0; it < NIT; it++) {
        const int cur = it & 1;
        if (it + 1 < NIT) {
            const float* ap = aptr + (it + 1) * BK;
            const float* bp = bptr + (it + 1) * BK;
            ra0 = *(const float4*)(ap);
            ra1 = *(const float4*)(ap + 4);
            rb0 = *(const float4*)(bp);
            rb1 = *(const float4*)(bp + 4);
        }
        #pragma unroll
        for (int k = 0; k < BK; k++) {
            const ulonglong2* ar = (const ulonglong2*)&As[cur][k * 128 + ty * 8];
            const ulonglong2* br = (const ulonglong2*)&Bs[cur][k * 128 + tx * 8];
            ulonglong2 a01 = ar[0], a23 = ar[1], a45 = ar[2], a67 = ar[3];
            ulonglong2 b01 = br[0], b23 = br[1];
            ull av[8] = {a01.x, a01.y, a23.x, a23.y, a45.x, a45.y, a67.x, a67.y};
            ull bv[4] = {b01.x, b01.y, b23.x, b23.y};
            #pragma unroll
            for (int m = 0; m < 8; m++)
                #pragma unroll
                for (int p = 0; p < 4; p++)
                    fma2(acc[m][p], av[m], bv[p]);
        }
        if (it + 1 < NIT) {
            const int nxt = cur ^ 1;
            float a[8] = {ra0.x, ra0.y, ra0.z, ra0.w, ra1.x, ra1.y, ra1.z, ra1.w};
            float b[8] = {rb0.x, rb0.y, rb0.z, rb0.w, rb1.x, rb1.y, rb1.z, rb1.w};
            #pragma unroll
            for (int j = 0; j < 8; j++) {
                As[nxt][(sk8 + j) * 128 + sm_] = make_float2(a[j], a[j]);
                Bs[nxt][(sk8 + j) * 128 + sm_] = b[j];
            }
        }
        __syncthreads();
    }

    #pragma unroll
    for (int m = 0; m < 8; m++) {
        float* orow = out + (size_t)(bm + ty * 8 + m) * THREE_H + bn + tx * 8;
        #pragma unroll
        for (int p = 0; p < 4; p++)
            ((ull*)orow)[p] = add2(acc[m][p], biasp[p]);
    }
}

// ---------------------------------------------------------------------------
// Persistent GRU recurrence — mma.sync bf16 split precision, LDG-direct A.
//
//  Per block/step: D[64,24] = h[64,1024] x Whh_slice[24,1024]^T.
//  Split precision: h = hi + lo (bf16 each), W = hi + lo; 3 HMMA terms
//  (hi*hi + lo*hi + hi*lo), fp32 accum -> rel_err ~1e-5.
//  16 warps = 4 m-tiles (16 b) x 4 k-slabs (256 k).  Per warp:
//  16 ksteps x { 8 x ld.global.cg A-frag regs, 12 LDS B-frag regs, 9 mma }.
//  No staging, no block syncs in mainloop.  4-way k-slab reduction via
//  24KB smem; epilogue = 1 (b,j) unit/thread, h_prev in a register,
//  h stored as bf16 hi/lo (ping-pong) + fp32 seq.
// ---------------------------------------------------------------------------
#define WROW    1032                       // bf16 units per W smem row
#define W_HI_B  0
#define W_LO_B  (24 * WROW * 2)            // 49536
#define RED_B   (2 * 24 * WROW * 2)        // 99072
#define RDYN_BYTES (RED_B + 16 * 32 * 12 * 4)   // 99072 + 24576 = 123648

__device__ __forceinline__ void grid_sync_() {
    __threadfence();
    __syncthreads();
    if (threadIdx.x == 0) {
        unsigned gen = *(volatile unsigned*)&g_bar_gen;
        unsigned ticket = atomicAdd(&g_bar_cnt, 1u);
        if (ticket == NBLK - 1) {
            g_bar_cnt = 0;
            __threadfence();
            atomicAdd(&g_bar_gen, 1u);
        } else {
            while (*(volatile unsigned*)&g_bar_gen == gen) __nanosleep(20);
        }
    }
    __syncthreads();
}

__global__ __launch_bounds__(NTHR, 1) void gru_persistent_kernel(
    const float* __restrict__ gi,     // [T, B, 3H] interleaved
    const float* __restrict__ whh,    // [3H, H]
    const float* __restrict__ bhh,    // [3H]
    const float* __restrict__ h0l,    // [B, H] this layer's h0
    float* __restrict__ seq_out,      // [T, B, H] or nullptr
    float* __restrict__ hlast)        // [B, H]
{
    extern __shared__ char dynb[];
    __nv_bfloat16* Whi = (__nv_bfloat16*)(dynb + W_HI_B);
    __nv_bfloat16* Wlo = (__nv_bfloat16*)(dynb + W_LO_B);
    float*         red = (float*)(dynb + RED_B);   // [16 w][32 lane][12]

    const int tid   = threadIdx.x;
    const int w     = tid >> 5;
    const int lane  = tid & 31;
    const int jbase = blockIdx.x * 8;

    // ---- convert Whh slice -> bf16 hi/lo smem (once) ----
    for (int idx = tid; idx < 24576; idx += NTHR) {
        int c = idx >> 10, k = idx & 1023;
        int row = (c % 3) * H_DIM + (jbase + c / 3);
        float wv = whh[(size_t)row * H_DIM + k];
        __nv_bfloat16 hi = __float2bfloat16(wv);
        Whi[c * WROW + k] = hi;
        Wlo[c * WROW + k] = __float2bfloat16(wv - __bfloat162float(hi));
    }

    // ---- init global h16 buffer 0 (each block: disjoint slice) ----
    {
        int idx = blockIdx.x * NTHR + tid;     // 128*512 = 65536 exactly
        int b = idx >> 10, k = idx & 1023;
        float v = h0l[b * H_DIM + k];
        __nv_bfloat16 hi = __float2bfloat16(v);
        g_h16hi[0][b * H_DIM + k] = hi;
        g_h16lo[0][b * H_DIM + k] = __float2bfloat16(v - __bfloat162float(hi));
    }

    // mainloop constants
    const int mtile = w & 3;            // m-tile (16 b rows)
    const int kslab = w >> 2;           // k-slab (256 k)
    const int rA    = mtile * 16 + (lane >> 2);
    const int cAoff = kslab * 256 + (lane & 3) * 2;
    const int cBoff = (lane & 3) * 2;
    const int nB    = lane >> 2;        // 0..7 within each n-tile

    // epilogue constants: thread owns (b = tid>>3, j = tid&7)
    const int ep_b  = tid >> 3;
    const int ep_j  = tid & 7;
    const int ep_jg = jbase + ep_j;
    const float br  = bhh[ep_jg];
    const float bz  = bhh[H_DIM + ep_jg];
    const float bn_ = bhh[2 * H_DIM + ep_jg];
    float hp_reg = h0l[ep_b * H_DIM + ep_jg];

    __syncthreads();

    const bool wr_seq = (seq_out != nullptr);

    for (int t = 0; t < T_STEPS; t++) {
        const __nv_bfloat16* hiIn = g_h16hi[t & 1];
        const __nv_bfloat16* loIn = g_h16lo[t & 1];
        __nv_bfloat16* hiOut = g_h16hi[(t + 1) & 1];
        __nv_bfloat16* loOut = g_h16lo[(t + 1) & 1];
        const float* gi_t = gi + (size_t)t * B_SZ * THREE_H;

        grid_sync_();   // prev-step h16 visible everywhere

        // prefetch epilogue gi operands
        float ga = __ldg(gi_t + (size_t)ep_b * THREE_H + ep_jg * 3 + 0);
        float gb = __ldg(gi_t + (size_t)ep_b * THREE_H + ep_jg * 3 + 1);
        float gc = __ldg(gi_t + (size_t)ep_b * THREE_H + ep_jg * 3 + 2);

        float acc[3][4];
        #pragma unroll
        for (int nt = 0; nt < 3; nt++)
            #pragma unroll
            for (int r = 0; r < 4; r++)
                acc[nt][r] = 0.0f;

        const uint32_t* hi0 = (const uint32_t*)(hiIn + (size_t)rA * H_DIM + cAoff);
        const uint32_t* hi1 = (const uint32_t*)(hiIn + (size_t)(rA + 8) * H_DIM + cAoff);
        const uint32_t* lo0 = (const uint32_t*)(loIn + (size_t)rA * H_DIM + cAoff);
        const uint32_t* lo1 = (const uint32_t*)(loIn + (size_t)(rA + 8) * H_DIM + cAoff);

        #pragma unroll
        for (int k = 0; k < 16; k++) {
            const int kw = k * 8;          // 16 bf16 = 8 uint32 per kstep
            uint32_t ah0 = __ldcg(hi0 + kw);
            uint32_t ah2 = __ldcg(hi0 + kw + 4);
            uint32_t ah1 = __ldcg(hi1 + kw);
            uint32_t ah3 = __ldcg(hi1 + kw + 4);
            uint32_t al0 = __ldcg(lo0 + kw);
            uint32_t al2 = __ldcg(lo0 + kw + 4);
            uint32_t al1 = __ldcg(lo1 + kw);
            uint32_t al3 = __ldcg(lo1 + kw + 4);

            const int kB = kslab * 256 + k * 16 + cBoff;
            #pragma unroll
            for (int nt = 0; nt < 3; nt++) {
                const __nv_bfloat16* wb = Whi + (nt * 8 + nB) * WROW + kB;
                const __nv_bfloat16* wl = Wlo + (nt * 8 + nB) * WROW + kB;
                uint32_t bh0 = *(const uint32_t*)(wb);
                uint32_t bh1 = *(const uint32_t*)(wb + 8);
                uint32_t bl0 = *(const uint32_t*)(wl);
                uint32_t bl1 = *(const uint32_t*)(wl + 8);
                mma_bf16(acc[nt], ah0, ah1, ah2, ah3, bh0, bh1);
                mma_bf16(acc[nt], al0, al1, al2, al3, bh0, bh1);
                mma_bf16(acc[nt], ah0, ah1, ah2, ah3, bl0, bl1);
            }
        }

        // ---- k-slab reduction via smem ----
        __syncthreads();
        {
            float* mine = red + (w * 32 + lane) * 12;
            #pragma unroll
            for (int nt = 0; nt < 3; nt++)
                #pragma unroll
                for (int r = 0; r < 4; r++)
                    mine[nt * 4 + r] = acc[nt][r];
        }
        __syncthreads();

        // ---- gate epilogue: 1 (b, j) unit per thread ----
        {
            const int m  = ep_b >> 4;
            const int bl = ep_b & 15;
            float s[3];
            #pragma unroll
            for (int g = 0; g < 3; g++) {
                int c   = ep_j * 3 + g;
                int nt  = c >> 3;
                int cr  = c & 7;
                int ln  = (bl & 7) * 4 + (cr >> 1);
                int rg  = ((bl >> 3) << 1) + (cr & 1);
                int idx = nt * 4 + rg;
                float acc_s = 0.f;
                #pragma unroll
                for (int ks = 0; ks < 4; ks++)
                    acc_s += red[((ks * 4 + m) * 32 + ln) * 12 + idx];
                s[g] = acc_s;
            }
            float r  = sigm(ga + s[0] + br);
            float z  = sigm(gb + s[1] + bz);
            float n  = tanhf(gc + r * (s[2] + bn_));
            float hn = (1.0f - z) * n + z * hp_reg;
            hp_reg = hn;
            __nv_bfloat16 hi = __float2bfloat16(hn);
            hiOut[ep_b * H_DIM + ep_jg] = hi;
            loOut[ep_b * H_DIM + ep_jg] =
                __float2bfloat16(hn - __bfloat162float(hi));
            if (wr_seq)
                seq_out[(size_t)t * (B_SZ * H_DIM) + (size_t)ep_b * H_DIM + ep_jg] = hn;
            if (t == T_STEPS - 1)
                hlast[(size_t)ep_b * H_DIM + ep_jg] = hn;
        }
        __syncthreads();   // red consumed before next step overwrites
    }
}

// ---------------------------------------------------------------------------
// Launch: per layer — gi GEMM, persistent HMMA recurrence.
// ---------------------------------------------------------------------------
extern "C" void kernel_launch(void* const* d_in, const int* in_sizes, int n_in,
                              void* d_out, int out_size)
{
    (void)in_sizes; (void)n_in; (void)out_size;

    const float* x    = (const float*)d_in[0];
    const float* h0   = (const float*)d_in[1];
    const float* w_ih = (const float*)d_in[2];
    const float* w_hh = (const float*)d_in[3];
    const float* b_ih = (const float*)d_in[4];
    const float* b_hh = (const float*)d_in[5];
    float* out = (float*)d_out;

    float* gi  = nullptr;
    float* seq = nullptr;
    cudaGetSymbolAddress((void**)&gi,  g_gi);
    cudaGetSymbolAddress((void**)&seq, g_seq);

    cudaFuncSetAttribute(gru_persistent_kernel,
                         cudaFuncAttributeMaxDynamicSharedMemorySize,
                         RDYN_BYTES);

    const size_t BH = (size_t)B_SZ * H_DIM;   // 65536
    dim3 ggrid(THREE_H / BN, M_ROWS / BM);    // (24, 128)

    for (int l = 0; l < L_NUM; l++) {
        const float* A = (l == 0) ? x : seq;
        gi_gemm_kernel<<<ggrid, 256>>>(A,
                                       w_ih + (size_t)l * THREE_H * K_DIM,
                                       b_ih + (size_t)l * THREE_H,
                                       gi);
        gru_persistent_kernel<<<NBLK, NTHR, RDYN_BYTES>>>(
            gi,
            w_hh + (size_t)l * THREE_H * H_DIM,
            b_hh + (size_t)l * THREE_H,
            h0 + (size_t)l * BH,
            (l < L_NUM - 1) ? seq : nullptr,
            out + (size_t)l * BH);
    }
}

// round 12
// speedup vs baseline: 1.7816x; 1.4690x over previous
#include <cuda_runtime.h>
#include <cuda_bf16.h>
#include <cstddef>
#include <cstdint>

// Problem constants
#define T_STEPS 256
#define B_SZ    64
#define K_DIM   1024
#define H_DIM   1024
#define L_NUM   3
#define THREE_H 3072
#define M_ROWS  16384
#define NBLK    128
#define NTHR    512

typedef unsigned long long ull;

// ---------------------------------------------------------------------------
// Scratch (device globals — allocation-free per harness rules)
// ---------------------------------------------------------------------------
__device__ float g_gi [(size_t)M_ROWS * THREE_H];   // [T*B, 3H] gate-interleaved
__device__ float g_seq[(size_t)M_ROWS * H_DIM];     // [T, B, H] layer output
// h ping-pong in MMA-A-fragment-native layout, split bf16 hi/lo:
//   u32 index = (mtile*64 + kstep)*128 + lane*4 + reg   (uint4 slot = .../4)
__device__ uint4 g_hfrag[2][2][8192];               // [pingpong][hi/lo][slots]
__device__ unsigned g_bar_cnt = 0;
__device__ unsigned g_bar_gen = 0;

// ---------------------------------------------------------------------------
// helpers
// ---------------------------------------------------------------------------
__device__ __forceinline__ void fma2(ull& d, ull a, ull b) {
    asm("fma.rn.f32x2 %0, %1, %2, %0;" : "+l"(d) : "l"(a), "l"(b));
}
__device__ __forceinline__ ull add2(ull a, ull b) {
    ull r;
    asm("add.rn.f32x2 %0, %1, %2;" : "=l"(r) : "l"(a), "l"(b));
    return r;
}
__device__ __forceinline__ float sigm(float x) { return 1.0f / (1.0f + expf(-x)); }

// bf16 HMMA: D[16,8] += A[16,16] * B[16,8]
__device__ __forceinline__ void mma_bf16(
    float* d, uint32_t a0, uint32_t a1, uint32_t a2, uint32_t a3,
    uint32_t b0, uint32_t b1)
{
    asm volatile(
        "mma.sync.aligned.m16n8k16.row.col.f32.bf16.bf16.f32 "
        "{%0,%1,%2,%3}, {%4,%5,%6,%7}, {%8,%9}, {%0,%1,%2,%3};"
        : "+f"(d[0]), "+f"(d[1]), "+f"(d[2]), "+f"(d[3])
        : "r"(a0), "r"(a1), "r"(a2), "r"(a3), "r"(b0), "r"(b1));
}

// ---------------------------------------------------------------------------
// Kernel 1: gi = A @ Wih^T + b_ih (cols gate-interleaved c = j*3+gate).
// (unchanged — f32x2, 128x128x16 tiles)
// ---------------------------------------------------------------------------
#define BM 128
#define BN 128
#define BK 16
#define NIT (K_DIM / BK)    // 64

__global__ __launch_bounds__(256, 2) void gi_gemm_kernel(
    const float* __restrict__ A, const float* __restrict__ W,
    const float* __restrict__ bias, float* __restrict__ out)
{
    __shared__ float2 As[2][BK * 128];
    __shared__ float  Bs[2][BK * 128];

    const int tid = threadIdx.x;
    const int tx  = tid & 15;
    const int ty  = tid >> 4;
    const int bm  = blockIdx.y * BM;
    const int bn  = blockIdx.x * BN;

    const int sm_ = tid >> 1;
    const int sk8 = (tid & 1) * 8;
    const float* aptr = A + (size_t)(bm + sm_) * K_DIM + sk8;
    const int    cB   = bn + sm_;
    const float* bptr = W + (size_t)((cB % 3) * H_DIM + cB / 3) * K_DIM + sk8;

    ull biasp[4];
    #pragma unroll
    for (int p = 0; p < 4; p++) {
        int c0 = bn + tx * 8 + 2 * p;
        float blo = bias[(c0 % 3) * H_DIM + c0 / 3];
        float bhi = bias[((c0 + 1) % 3) * H_DIM + (c0 + 1) / 3];
        float2 bp = make_float2(blo, bhi);
        biasp[p] = *(ull*)&bp;
    }

    ull acc[8][4];
    #pragma unroll
    for (int m = 0; m < 8; m++)
        #pragma unroll
        for (int p = 0; p < 4; p++)
            acc[m][p] = 0ull;

    float4 ra0 = *(const float4*)(aptr);
    float4 ra1 = *(const float4*)(aptr + 4);
    float4 rb0 = *(const float4*)(bptr);
    float4 rb1 = *(const float4*)(bptr + 4);
    {
        float a[8] = {ra0.x, ra0.y, ra0.z, ra0.w, ra1.x, ra1.y, ra1.z, ra1.w};
        float b[8] = {rb0.x, rb0.y, rb0.z, rb0.w, rb1.x, rb1.y, rb1.z, rb1.w};
        #pragma unroll
        for (int j = 0; j < 8; j++) {
            As[0][(sk8 + j) * 128 + sm_] = make_float2(a[j], a[j]);
            Bs[0][(sk8 + j) * 128 + sm_] = b[j];
        }
    }
    __syncthreads();

    for (int it = 0; it < NIT; it++) {
        const int cur = it & 1;
        if (it + 1 < NIT) {
            const float* ap = aptr + (it + 1) * BK;
            const float* bp = bptr + (it + 1) * BK;
            ra0 = *(const float4*)(ap);
            ra1 = *(const float4*)(ap + 4);
            rb0 = *(const float4*)(bp);
            rb1 = *(const float4*)(bp + 4);
        }
        #pragma unroll
        for (int k = 0; k < BK; k++) {
            const ulonglong2* ar = (const ulonglong2*)&As[cur][k * 128 + ty * 8];
            const ulonglong2* br = (const ulonglong2*)&Bs[cur][k * 128 + tx * 8];
            ulonglong2 a01 = ar[0], a23 = ar[1], a45 = ar[2], a67 = ar[3];
            ulonglong2 b01 = br[0], b23 = br[1];
            ull av[8] = {a01.x, a01.y, a23.x, a23.y, a45.x, a45.y, a67.x, a67.y};
            ull bv[4] = {b01.x, b01.y, b23.x, b23.y};
            #pragma unroll
            for (int m = 0; m < 8; m++)
                #pragma unroll
                for (int p = 0; p < 4; p++)
                    fma2(acc[m][p], av[m], bv[p]);
        }
        if (it + 1 < NIT) {
            const int nxt = cur ^ 1;
            float a[8] = {ra0.x, ra0.y, ra0.z, ra0.w, ra1.x, ra1.y, ra1.z, ra1.w};
            float b[8] = {rb0.x, rb0.y, rb0.z, rb0.w, rb1.x, rb1.y, rb1.z, rb1.w};
            #pragma unroll
            for (int j = 0; j < 8; j++) {
                As[nxt][(sk8 + j) * 128 + sm_] = make_float2(a[j], a[j]);
                Bs[nxt][(sk8 + j) * 128 + sm_] = b[j];
            }
        }
        __syncthreads();
    }

    #pragma unroll
    for (int m = 0; m < 8; m++) {
        float* orow = out + (size_t)(bm + ty * 8 + m) * THREE_H + bn + tx * 8;
        #pragma unroll
        for (int p = 0; p < 4; p++)
            ((ull*)orow)[p] = add2(acc[m][p], biasp[p]);
    }
}

// ---------------------------------------------------------------------------
// Persistent GRU recurrence — mma.sync bf16, fragment-native h layout.
//
//  D[64,24] = h[64,1024] x Whh_slice[24,1024]^T per block/step; split
//  precision (3 HMMA terms), 16 warps = 4 mtiles x 4 kslabs.
//  h stored globally in A-fragment order -> per kstep per precision ONE
//  coalesced LDG.128 per warp (4 L1tex wavefronts, was 32).
//  W repacked in smem as uint4 {bh0,bh1,bl0,bl1} frag slots -> LDS.128.
//  Epilogue: 1 (b,j)/thread, h_prev in reg, scattered 2B stores into the
//  fragment layout of the ping-pong target buffer.
// ---------------------------------------------------------------------------
#define WF_BYTES   98304                    // 3 nt * 64 kstep * 32 lanes * 16B
#define RED_B      WF_BYTES
#define RDYN_BYTES (WF_BYTES + 16 * 32 * 12 * 4)   // + 24576 = 122880

__device__ __forceinline__ void grid_sync_() {
    __threadfence();
    __syncthreads();
    if (threadIdx.x == 0) {
        unsigned gen = *(volatile unsigned*)&g_bar_gen;
        unsigned ticket = atomicAdd(&g_bar_cnt, 1u);
        if (ticket == NBLK - 1) {
            g_bar_cnt = 0;
            __threadfence();
            atomicAdd(&g_bar_gen, 1u);
        } else {
            while (*(volatile unsigned*)&g_bar_gen == gen) __nanosleep(20);
        }
    }
    __syncthreads();
}

// fragment address (bf16 units) of element (row b, col k) in a frag buffer
__device__ __forceinline__ int frag_addr_bf16(int b, int k) {
    int mt  = b >> 4, rr = b & 15;
    int ks  = k >> 4, c16 = k & 15;
    int rg  = (rr >> 3) | ((c16 >> 3) << 1);
    int ln  = (rr & 7) * 4 + ((c16 & 7) >> 1);
    int u32 = (mt * 64 + ks) * 128 + ln * 4 + rg;
    return u32 * 2 + (c16 & 1);
}

__global__ __launch_bounds__(NTHR, 1) void gru_persistent_kernel(
    const float* __restrict__ gi,     // [T, B, 3H] interleaved
    const float* __restrict__ whh,    // [3H, H]
    const float* __restrict__ bhh,    // [3H]
    const float* __restrict__ h0l,    // [B, H] this layer's h0
    float* __restrict__ seq_out,      // [T, B, H] or nullptr
    float* __restrict__ hlast)        // [B, H]
{
    extern __shared__ char dynb[];
    uint4* Wf  = (uint4*)dynb;                 // [3 nt][64 kstep][32] frag slots
    float* red = (float*)(dynb + RED_B);       // [16 w][32 lane][12]

    const int tid   = threadIdx.x;
    const int w     = tid >> 5;
    const int lane  = tid & 31;
    const int jbase = blockIdx.x * 8;

    // ---- convert Whh slice -> bf16 hi/lo fragment smem (once) ----
    {
        __nv_bfloat16* Wb = (__nv_bfloat16*)Wf;
        for (int idx = tid; idx < 24576; idx += NTHR) {
            int c = idx >> 10, k = idx & 1023;
            int row = (c % 3) * H_DIM + (jbase + c / 3);
            float wv = whh[(size_t)row * H_DIM + k];
            __nv_bfloat16 hi = __float2bfloat16(wv);
            __nv_bfloat16 lo = __float2bfloat16(wv - __bfloat162float(hi));
            int nt = c >> 3, n8 = c & 7;
            int ks = k >> 4, c16 = k & 15;
            int ln = n8 * 4 + ((c16 & 7) >> 1);
            int br = c16 >> 3;
            int hf = c16 & 1;
            size_t o = ((size_t)(nt * 64 + ks) * 32 + ln) * 8 + br * 2 + hf;
            Wb[o]     = hi;     // comps x/y = hi b0/b1
            Wb[o + 4] = lo;     // comps z/w = lo b0/b1
        }
    }

    // ---- init global h fragment buffer 0 (each block: disjoint slice) ----
    {
        int idx = blockIdx.x * NTHR + tid;     // 128*512 = 65536 exactly
        int b = idx >> 10, k = idx & 1023;
        float v = h0l[b * H_DIM + k];
        __nv_bfloat16 hi = __float2bfloat16(v);
        int fa = frag_addr_bf16(b, k);
        ((__nv_bfloat16*)g_hfrag[0][0])[fa] = hi;
        ((__nv_bfloat16*)g_hfrag[0][1])[fa] =
            __float2bfloat16(v - __bfloat162float(hi));
    }

    // mainloop constants
    const int mtile = w & 3;            // m-tile (16 b rows)
    const int kslab = w >> 2;           // k-slab (16 ksteps)
    const int aoff  = (mtile * 64 + kslab * 16) * 32 + lane;   // uint4 idx

    // epilogue constants: thread owns (b = tid>>3, j = tid&7)
    const int ep_b  = tid >> 3;
    const int ep_j  = tid & 7;
    const int ep_jg = jbase + ep_j;
    const float br  = bhh[ep_jg];
    const float bz  = bhh[H_DIM + ep_jg];
    const float bn_ = bhh[2 * H_DIM + ep_jg];
    const int ep_fa = frag_addr_bf16(ep_b, ep_jg);
    float hp_reg = h0l[ep_b * H_DIM + ep_jg];

    __syncthreads();

    const bool wr_seq = (seq_out != nullptr);

    for (int t = 0; t < T_STEPS; t++) {
        const uint4* Ahi = g_hfrag[t & 1][0] + aoff;
        const uint4* Alo = g_hfrag[t & 1][1] + aoff;
        __nv_bfloat16* hiOut = (__nv_bfloat16*)g_hfrag[(t + 1) & 1][0] + ep_fa;
        __nv_bfloat16* loOut = (__nv_bfloat16*)g_hfrag[(t + 1) & 1][1] + ep_fa;
        const float* gi_t = gi + (size_t)t * B_SZ * THREE_H;

        grid_sync_();   // prev-step h fragments visible everywhere

        // prefetch epilogue gi operands
        float ga = __ldg(gi_t + (size_t)ep_b * THREE_H + ep_jg * 3 + 0);
        float gb = __ldg(gi_t + (size_t)ep_b * THREE_H + ep_jg * 3 + 1);
        float gc = __ldg(gi_t + (size_t)ep_b * THREE_H + ep_jg * 3 + 2);

        float acc[3][4];
        #pragma unroll
        for (int nt = 0; nt < 3; nt++)
            #pragma unroll
            for (int r = 0; r < 4; r++)
                acc[nt][r] = 0.0f;

        #pragma unroll
        for (int k = 0; k < 16; k++) {
            uint4 ah = __ldcg(Ahi + k * 32);
            uint4 al = __ldcg(Alo + k * 32);
            const int kg = kslab * 16 + k;
            #pragma unroll
            for (int nt = 0; nt < 3; nt++) {
                uint4 bv = Wf[(nt * 64 + kg) * 32 + lane];
                mma_bf16(acc[nt], ah.x, ah.y, ah.z, ah.w, bv.x, bv.y);
                mma_bf16(acc[nt], al.x, al.y, al.z, al.w, bv.x, bv.y);
                mma_bf16(acc[nt], ah.x, ah.y, ah.z, ah.w, bv.z, bv.w);
            }
        }

        // ---- k-slab reduction via smem ----
        __syncthreads();
        {
            float* mine = red + (w * 32 + lane) * 12;
            #pragma unroll
            for (int nt = 0; nt < 3; nt++)
                #pragma unroll
                for (int r = 0; r < 4; r++)
                    mine[nt * 4 + r] = acc[nt][r];
        }
        __syncthreads();

        // ---- gate epilogue: 1 (b, j) unit per thread ----
        {
            const int m  = ep_b >> 4;
            const int bl = ep_b & 15;
            float s[3];
            #pragma unroll
            for (int g = 0; g < 3; g++) {
                int c   = ep_j * 3 + g;
                int nt  = c >> 3;
                int cr  = c & 7;
                int ln  = (bl & 7) * 4 + (cr >> 1);
                int rg  = ((bl >> 3) << 1) + (cr & 1);
                int idx = nt * 4 + rg;
                float acc_s = 0.f;
                #pragma unroll
                for (int ks = 0; ks < 4; ks++)
                    acc_s += red[((ks * 4 + m) * 32 + ln) * 12 + idx];
                s[g] = acc_s;
            }
            float r  = sigm(ga + s[0] + br);
            float z  = sigm(gb + s[1] + bz);
            float n  = tanhf(gc + r * (s[2] + bn_));
            float hn = (1.0f - z) * n + z * hp_reg;
            hp_reg = hn;
            __nv_bfloat16 hi = __float2bfloat16(hn);
            *hiOut = hi;
            *loOut = __float2bfloat16(hn - __bfloat162float(hi));
            if (wr_seq)
                seq_out[(size_t)t * (B_SZ * H_DIM) + (size_t)ep_b * H_DIM + ep_jg] = hn;
            if (t == T_STEPS - 1)
                hlast[(size_t)ep_b * H_DIM + ep_jg] = hn;
        }
        __syncthreads();   // red consumed before next step overwrites
    }
}

// ---------------------------------------------------------------------------
// Launch: per layer — gi GEMM, persistent HMMA recurrence.
// ---------------------------------------------------------------------------
extern "C" void kernel_launch(void* const* d_in, const int* in_sizes, int n_in,
                              void* d_out, int out_size)
{
    (void)in_sizes; (void)n_in; (void)out_size;

    const float* x    = (const float*)d_in[0];
    const float* h0   = (const float*)d_in[1];
    const float* w_ih = (const float*)d_in[2];
    const float* w_hh = (const float*)d_in[3];
    const float* b_ih = (const float*)d_in[4];
    const float* b_hh = (const float*)d_in[5];
    float* out = (float*)d_out;

    float* gi  = nullptr;
    float* seq = nullptr;
    cudaGetSymbolAddress((void**)&gi,  g_gi);
    cudaGetSymbolAddress((void**)&seq, g_seq);

    cudaFuncSetAttribute(gru_persistent_kernel,
                         cudaFuncAttributeMaxDynamicSharedMemorySize,
                         RDYN_BYTES);

    const size_t BH = (size_t)B_SZ * H_DIM;   // 65536
    dim3 ggrid(THREE_H / BN, M_ROWS / BM);    // (24, 128)

    for (int l = 0; l < L_NUM; l++) {
        const float* A = (l == 0) ? x : seq;
        gi_gemm_kernel<<<ggrid, 256>>>(A,
                                       w_ih + (size_t)l * THREE_H * K_DIM,
                                       b_ih + (size_t)l * THREE_H,
                                       gi);
        gru_persistent_kernel<<<NBLK, NTHR, RDYN_BYTES>>>(
            gi,
            w_hh + (size_t)l * THREE_H * H_DIM,
            b_hh + (size_t)l * THREE_H,
            h0 + (size_t)l * BH,
            (l < L_NUM - 1) ? seq : nullptr,
            out + (size_t)l * BH);
    }
}

// round 13
// speedup vs baseline: 3.1283x; 1.7559x over previous
#include <cuda_runtime.h>
#include <cuda_bf16.h>
#include <cstddef>
#include <cstdint>

// Problem constants
#define T_STEPS 256
#define B_SZ    64
#define K_DIM   1024
#define H_DIM   1024
#define L_NUM   3
#define THREE_H 3072
#define M_ROWS  16384
#define NBLK    128
#define NTHR    512

typedef unsigned long long ull;

// ---------------------------------------------------------------------------
// Scratch (device globals — allocation-free per harness rules)
// ---------------------------------------------------------------------------
__device__ float g_gi [(size_t)M_ROWS * THREE_H];   // [T*B, 3H] gate-interleaved
// bf16 hi/lo copies of x and of each layer's output sequence
__device__ __nv_bfloat16 g_x16hi[(size_t)M_ROWS * K_DIM];
__device__ __nv_bfloat16 g_x16lo[(size_t)M_ROWS * K_DIM];
__device__ __nv_bfloat16 g_s16hi[(size_t)M_ROWS * K_DIM];
__device__ __nv_bfloat16 g_s16lo[(size_t)M_ROWS * K_DIM];
// W_ih permuted (gate-interleaved col order) bf16 hi/lo: [(l*3072+n)*1024+k]
__device__ __nv_bfloat16 g_w16hi[(size_t)L_NUM * THREE_H * K_DIM];
__device__ __nv_bfloat16 g_w16lo[(size_t)L_NUM * THREE_H * K_DIM];
// h ping-pong in MMA-A-fragment-native layout, split bf16 hi/lo
__device__ uint4 g_hfrag[2][2][8192];               // [pingpong][hi/lo][slots]
__device__ unsigned g_bar_cnt = 0;
__device__ unsigned g_bar_gen = 0;

// ---------------------------------------------------------------------------
// helpers
// ---------------------------------------------------------------------------
__device__ __forceinline__ float sigm(float x) { return 1.0f / (1.0f + expf(-x)); }

__device__ __forceinline__ void mma_bf16(
    float* d, uint32_t a0, uint32_t a1, uint32_t a2, uint32_t a3,
    uint32_t b0, uint32_t b1)
{
    asm volatile(
        "mma.sync.aligned.m16n8k16.row.col.f32.bf16.bf16.f32 "
        "{%0,%1,%2,%3}, {%4,%5,%6,%7}, {%8,%9}, {%0,%1,%2,%3};"
        : "+f"(d[0]), "+f"(d[1]), "+f"(d[2]), "+f"(d[3])
        : "r"(a0), "r"(a1), "r"(a2), "r"(a3), "r"(b0), "r"(b1));
}
__device__ __forceinline__ void ldm_x4(uint32_t* r, uint32_t saddr) {
    asm volatile("ldmatrix.sync.aligned.m8n8.x4.shared.b16 {%0,%1,%2,%3}, [%4];"
        : "=r"(r[0]), "=r"(r[1]), "=r"(r[2]), "=r"(r[3]) : "r"(saddr));
}
__device__ __forceinline__ void cp16(void* dst, const void* src) {
    unsigned sa = (unsigned)__cvta_generic_to_shared(dst);
    asm volatile("cp.async.cg.shared.global [%0], [%1], 16;" :: "r"(sa), "l"(src));
}
__device__ __forceinline__ void cp_commit() {
    asm volatile("cp.async.commit_group;" ::: "memory");
}
template <int N>
__device__ __forceinline__ void cp_wait() {
    asm volatile("cp.async.wait_group %0;" :: "n"(N) : "memory");
}

// ---------------------------------------------------------------------------
// Conversion kernels (run once per launch)
// ---------------------------------------------------------------------------
__global__ __launch_bounds__(256) void conv_x_kernel(
    const float* __restrict__ x,
    __nv_bfloat16* __restrict__ hi, __nv_bfloat16* __restrict__ lo)
{
    size_t i = (size_t)blockIdx.x * 256 + threadIdx.x;   // 16777216 total
    float v = x[i];
    __nv_bfloat16 h = __float2bfloat16(v);
    hi[i] = h;
    lo[i] = __float2bfloat16(v - __bfloat162float(h));
}

__global__ __launch_bounds__(256) void conv_w_kernel(
    const float* __restrict__ wih,
    __nv_bfloat16* __restrict__ hi, __nv_bfloat16* __restrict__ lo)
{
    size_t i = (size_t)blockIdx.x * 256 + threadIdx.x;   // 9437184 total
    int k   = (int)(i & 1023);
    int r10 = (int)(i >> 10);
    int l   = r10 / THREE_H;
    int n   = r10 - l * THREE_H;
    int row = (n % 3) * H_DIM + n / 3;
    float v = wih[((size_t)l * THREE_H + row) * K_DIM + k];
    __nv_bfloat16 h = __float2bfloat16(v);
    hi[i] = h;
    lo[i] = __float2bfloat16(v - __bfloat162float(h));
}

// ---------------------------------------------------------------------------
// Kernel 1: gi = A @ W^T + bias — bf16 HMMA, 3-term split precision.
// A: [16384][1024] bf16 hi/lo; W: permuted [3072][1024] bf16 hi/lo.
// Block: 128m x 128n, BK=64, 8 warps (warp tile 64x32), double-buffered
// cp.async staging, ldmatrix fragments (stride-72 smem, conflict-free).
// ---------------------------------------------------------------------------
#define GTILE_B   18432                 // one 128x72 bf16 tile, bytes
#define GSTAGE_B  (4 * GTILE_B)         // Ah, Al, Wh, Wl
#define GI_SMEM   (2 * GSTAGE_B)        // 147456

__global__ __launch_bounds__(256, 1) void gi_gemm_bf16_kernel(
    const __nv_bfloat16* __restrict__ Ahi,
    const __nv_bfloat16* __restrict__ Alo,
    const __nv_bfloat16* __restrict__ Whi,
    const __nv_bfloat16* __restrict__ Wlo,
    const float* __restrict__ bias,     // layer slice of b_ih [3H]
    float* __restrict__ out)
{
    extern __shared__ char gsm[];
    const uint32_t smb = (uint32_t)__cvta_generic_to_shared(gsm);

    const int tid  = threadIdx.x;
    const int w    = tid >> 5;
    const int lane = tid & 31;
    const int wm   = w >> 2;            // 0..1  (64 m rows)
    const int wn   = w & 3;             // 0..3  (32 n cols)
    const int bm   = blockIdx.y * 128;
    const int bn   = blockIdx.x * 128;

    // staging source pointers (per tile id 0..3)
    const int s_r  = (tid >> 3) & 31;   // not used directly; see loop
    (void)s_r;
    const __nv_bfloat16* srcs[4] = {
        Ahi + (size_t)bm * K_DIM, Alo + (size_t)bm * K_DIM,
        Whi + (size_t)bn * K_DIM, Wlo + (size_t)bn * K_DIM
    };

    // per-thread bias (4 ntiles x 2 cols)
    float bias_v[4][2];
    #pragma unroll
    for (int nt = 0; nt < 4; nt++) {
        int n0 = bn + wn * 32 + nt * 8 + (lane & 3) * 2;
        bias_v[nt][0] = bias[(n0 % 3) * H_DIM + n0 / 3];
        bias_v[nt][1] = bias[((n0 + 1) % 3) * H_DIM + (n0 + 1) / 3];
    }

    float acc[4][4][4];
    #pragma unroll
    for (int mt = 0; mt < 4; mt++)
        #pragma unroll
        for (int nt = 0; nt < 4; nt++)
            #pragma unroll
            for (int r = 0; r < 4; r++)
                acc[mt][nt][r] = 0.0f;

    // fragment address offsets (bytes, within a tile)
    const uint32_t aRowOff = (uint32_t)((wm * 64 + (lane & 15)) * 144 + (lane >> 4) * 16);
    const uint32_t bRowOff = (uint32_t)((wn * 32 + ((lane >> 4) & 1) * 8 + (lane & 7)) * 144
                                        + ((lane >> 3) & 1) * 16);

    // ---- staging macro: one 64-k tile set into stage s ----
    #define GSTAGE(kt, s)                                                      \
    {                                                                          \
        const int k0 = (kt) * 64;                                              \
        _Pragma("unroll")                                                      \
        for (int i = 0; i < 16; i++) {                                         \
            int idx  = i * 256 + tid;                                          \
            int tile = idx >> 10;                                              \
            int r    = (idx >> 3) & 127;                                       \
            int c8   = idx & 7;                                                \
            cp16(gsm + (s) * GSTAGE_B + tile * GTILE_B + r * 144 + c8 * 16,    \
                 srcs[tile] + (size_t)r * K_DIM + k0 + c8 * 8);                \
        }                                                                      \
        cp_commit();                                                           \
    }

    GSTAGE(0, 0);

    for (int kt = 0; kt < 16; kt++) {
        if (kt < 15) {
            GSTAGE(kt + 1, (kt + 1) & 1);
            cp_wait<1>();
        } else {
            cp_wait<0>();
        }
        __syncthreads();

        const uint32_t sb  = smb + (kt & 1) * GSTAGE_B;
        const uint32_t sAh = sb;
        const uint32_t sAl = sb + GTILE_B;
        const uint32_t sWh = sb + 2 * GTILE_B;
        const uint32_t sWl = sb + 3 * GTILE_B;

        #pragma unroll
        for (int k16 = 0; k16 < 4; k16++) {
            uint32_t ah[4][4], al[4][4];
            #pragma unroll
            for (int mt = 0; mt < 4; mt++) {
                uint32_t ao = aRowOff + mt * 16 * 144 + k16 * 32;
                ldm_x4(ah[mt], sAh + ao);
                ldm_x4(al[mt], sAl + ao);
            }
            uint32_t bh[2][4], bl[2][4];
            #pragma unroll
            for (int np = 0; np < 2; np++) {
                uint32_t bo = bRowOff + np * 16 * 144 + k16 * 32;
                ldm_x4(bh[np], sWh + bo);
                ldm_x4(bl[np], sWl + bo);
            }
            #pragma unroll
            for (int mt = 0; mt < 4; mt++)
                #pragma unroll
                for (int nt = 0; nt < 4; nt++) {
                    uint32_t b0h = bh[nt >> 1][(nt & 1) * 2];
                    uint32_t b1h = bh[nt >> 1][(nt & 1) * 2 + 1];
                    uint32_t b0l = bl[nt >> 1][(nt & 1) * 2];
                    uint32_t b1l = bl[nt >> 1][(nt & 1) * 2 + 1];
                    mma_bf16(acc[mt][nt], ah[mt][0], ah[mt][1], ah[mt][2], ah[mt][3], b0h, b1h);
                    mma_bf16(acc[mt][nt], al[mt][0], al[mt][1], al[mt][2], al[mt][3], b0h, b1h);
                    mma_bf16(acc[mt][nt], ah[mt][0], ah[mt][1], ah[mt][2], ah[mt][3], b0l, b1l);
                }
        }
        __syncthreads();
    }
    #undef GSTAGE

    // epilogue: fp32 stores with permuted bias
    #pragma unroll
    for (int mt = 0; mt < 4; mt++) {
        int m = bm + wm * 64 + mt * 16 + (lane >> 2);
        #pragma unroll
        for (int nt = 0; nt < 4; nt++) {
            int n = bn + wn * 32 + nt * 8 + (lane & 3) * 2;
            float2 v0 = make_float2(acc[mt][nt][0] + bias_v[nt][0],
                                    acc[mt][nt][1] + bias_v[nt][1]);
            float2 v1 = make_float2(acc[mt][nt][2] + bias_v[nt][0],
                                    acc[mt][nt][3] + bias_v[nt][1]);
            *(float2*)(out + (size_t)m * THREE_H + n)       = v0;
            *(float2*)(out + (size_t)(m + 8) * THREE_H + n) = v1;
        }
    }
}

// ---------------------------------------------------------------------------
// Persistent GRU recurrence — mma.sync bf16, fragment-native h layout.
// (identical to R11 passing kernel except seq written as bf16 hi/lo)
// ---------------------------------------------------------------------------
#define WF_BYTES   98304                    // 3 nt * 64 kstep * 32 lanes * 16B
#define RED_B      WF_BYTES
#define RDYN_BYTES (WF_BYTES + 16 * 32 * 12 * 4)   // + 24576 = 122880

__device__ __forceinline__ void grid_sync_() {
    __threadfence();
    __syncthreads();
    if (threadIdx.x == 0) {
        unsigned gen = *(volatile unsigned*)&g_bar_gen;
        unsigned ticket = atomicAdd(&g_bar_cnt, 1u);
        if (ticket == NBLK - 1) {
            g_bar_cnt = 0;
            __threadfence();
            atomicAdd(&g_bar_gen, 1u);
        } else {
            while (*(volatile unsigned*)&g_bar_gen == gen) __nanosleep(20);
        }
    }
    __syncthreads();
}

// fragment address (bf16 units) of element (row b, col k) in a frag buffer
__device__ __forceinline__ int frag_addr_bf16(int b, int k) {
    int mt  = b >> 4, rr = b & 15;
    int ks  = k >> 4, c16 = k & 15;
    int rg  = (rr >> 3) | ((c16 >> 3) << 1);
    int ln  = (rr & 7) * 4 + ((c16 & 7) >> 1);
    int u32 = (mt * 64 + ks) * 128 + ln * 4 + rg;
    return u32 * 2 + (c16 & 1);
}

__global__ __launch_bounds__(NTHR, 1) void gru_persistent_kernel(
    const float* __restrict__ gi,     // [T, B, 3H] interleaved
    const float* __restrict__ whh,    // [3H, H]
    const float* __restrict__ bhh,    // [3H]
    const float* __restrict__ h0l,    // [B, H] this layer's h0
    __nv_bfloat16* __restrict__ s16hi, // [T*B, H] or nullptr
    __nv_bfloat16* __restrict__ s16lo,
    float* __restrict__ hlast)        // [B, H]
{
    extern __shared__ char dynb[];
    uint4* Wf  = (uint4*)dynb;                 // [3 nt][64 kstep][32] frag slots
    float* red = (float*)(dynb + RED_B);       // [16 w][32 lane][12]

    const int tid   = threadIdx.x;
    const int w     = tid >> 5;
    const int lane  = tid & 31;
    const int jbase = blockIdx.x * 8;

    // ---- convert Whh slice -> bf16 hi/lo fragment smem (once) ----
    {
        __nv_bfloat16* Wb = (__nv_bfloat16*)Wf;
        for (int idx = tid; idx < 24576; idx += NTHR) {
            int c = idx >> 10, k = idx & 1023;
            int row = (c % 3) * H_DIM + (jbase + c / 3);
            float wv = whh[(size_t)row * H_DIM + k];
            __nv_bfloat16 hi = __float2bfloat16(wv);
            __nv_bfloat16 lo = __float2bfloat16(wv - __bfloat162float(hi));
            int nt = c >> 3, n8 = c & 7;
            int ks = k >> 4, c16 = k & 15;
            int ln = n8 * 4 + ((c16 & 7) >> 1);
            int br = c16 >> 3;
            int hf = c16 & 1;
            size_t o = ((size_t)(nt * 64 + ks) * 32 + ln) * 8 + br * 2 + hf;
            Wb[o]     = hi;
            Wb[o + 4] = lo;
        }
    }

    // ---- init global h fragment buffer 0 (each block: disjoint slice) ----
    {
        int idx = blockIdx.x * NTHR + tid;     // 128*512 = 65536 exactly
        int b = idx >> 10, k = idx & 1023;
        float v = h0l[b * H_DIM + k];
        __nv_bfloat16 hi = __float2bfloat16(v);
        int fa = frag_addr_bf16(b, k);
        ((__nv_bfloat16*)g_hfrag[0][0])[fa] = hi;
        ((__nv_bfloat16*)g_hfrag[0][1])[fa] =
            __float2bfloat16(v - __bfloat162float(hi));
    }

    // mainloop constants
    const int mtile = w & 3;
    const int kslab = w >> 2;
    const int aoff  = (mtile * 64 + kslab * 16) * 32 + lane;   // uint4 idx

    // epilogue constants: thread owns (b = tid>>3, j = tid&7)
    const int ep_b  = tid >> 3;
    const int ep_j  = tid & 7;
    const int ep_jg = jbase + ep_j;
    const float br  = bhh[ep_jg];
    const float bz  = bhh[H_DIM + ep_jg];
    const float bn_ = bhh[2 * H_DIM + ep_jg];
    const int ep_fa = frag_addr_bf16(ep_b, ep_jg);
    float hp_reg = h0l[ep_b * H_DIM + ep_jg];

    __syncthreads();

    const bool wr_seq = (s16hi != nullptr);

    for (int t = 0; t < T_STEPS; t++) {
        const uint4* Ahi = g_hfrag[t & 1][0] + aoff;
        const uint4* Alo = g_hfrag[t & 1][1] + aoff;
        __nv_bfloat16* hiOut = (__nv_bfloat16*)g_hfrag[(t + 1) & 1][0] + ep_fa;
        __nv_bfloat16* loOut = (__nv_bfloat16*)g_hfrag[(t + 1) & 1][1] + ep_fa;
        const float* gi_t = gi + (size_t)t * B_SZ * THREE_H;

        grid_sync_();   // prev-step h fragments visible everywhere

        float ga = __ldg(gi_t + (size_t)ep_b * THREE_H + ep_jg * 3 + 0);
        float gb = __ldg(gi_t + (size_t)ep_b * THREE_H + ep_jg * 3 + 1);
        float gc = __ldg(gi_t + (size_t)ep_b * THREE_H + ep_jg * 3 + 2);

        float acc[3][4];
        #pragma unroll
        for (int nt = 0; nt < 3; nt++)
            #pragma unroll
            for (int r = 0; r < 4; r++)
                acc[nt][r] = 0.0f;

        #pragma unroll
        for (int k = 0; k < 16; k++) {
            uint4 ah = __ldcg(Ahi + k * 32);
            uint4 al = __ldcg(Alo + k * 32);
            const int kg = kslab * 16 + k;
            #pragma unroll
            for (int nt = 0; nt < 3; nt++) {
                uint4 bv = Wf[(nt * 64 + kg) * 32 + lane];
                mma_bf16(acc[nt], ah.x, ah.y, ah.z, ah.w, bv.x, bv.y);
                mma_bf16(acc[nt], al.x, al.y, al.z, al.w, bv.x, bv.y);
                mma_bf16(acc[nt], ah.x, ah.y, ah.z, ah.w, bv.z, bv.w);
            }
        }

        __syncthreads();
        {
            float* mine = red + (w * 32 + lane) * 12;
            #pragma unroll
            for (int nt = 0; nt < 3; nt++)
                #pragma unroll
                for (int r = 0; r < 4; r++)
                    mine[nt * 4 + r] = acc[nt][r];
        }
        __syncthreads();

        {
            const int m  = ep_b >> 4;
            const int bl = ep_b & 15;
            float s[3];
            #pragma unroll
            for (int g = 0; g < 3; g++) {
                int c   = ep_j * 3 + g;
                int nt  = c >> 3;
                int cr  = c & 7;
                int ln  = (bl & 7) * 4 + (cr >> 1);
                int rg  = ((bl >> 3) << 1) + (cr & 1);
                int idx = nt * 4 + rg;
                float acc_s = 0.f;
                #pragma unroll
                for (int ks = 0; ks < 4; ks++)
                    acc_s += red[((ks * 4 + m) * 32 + ln) * 12 + idx];
                s[g] = acc_s;
            }
            float r  = sigm(ga + s[0] + br);
            float z  = sigm(gb + s[1] + bz);
            float n  = tanhf(gc + r * (s[2] + bn_));
            float hn = (1.0f - z) * n + z * hp_reg;
            hp_reg = hn;
            __nv_bfloat16 hi = __float2bfloat16(hn);
            __nv_bfloat16 lo = __float2bfloat16(hn - __bfloat162float(hi));
            *hiOut = hi;
            *loOut = lo;
            if (wr_seq) {
                size_t so = ((size_t)t * B_SZ + ep_b) * H_DIM + ep_jg;
                s16hi[so] = hi;
                s16lo[so] = lo;
            }
            if (t == T_STEPS - 1)
                hlast[(size_t)ep_b * H_DIM + ep_jg] = hn;
        }
        __syncthreads();
    }
}

// ---------------------------------------------------------------------------
// Launch: conversions once, then per layer — bf16 gi GEMM + recurrence.
// ---------------------------------------------------------------------------
extern "C" void kernel_launch(void* const* d_in, const int* in_sizes, int n_in,
                              void* d_out, int out_size)
{
    (void)in_sizes; (void)n_in; (void)out_size;

    const float* x    = (const float*)d_in[0];
    const float* h0   = (const float*)d_in[1];
    const float* w_ih = (const float*)d_in[2];
    const float* w_hh = (const float*)d_in[3];
    const float* b_ih = (const float*)d_in[4];
    const float* b_hh = (const float*)d_in[5];
    float* out = (float*)d_out;

    float* gi = nullptr;
    __nv_bfloat16 *xhi = nullptr, *xlo = nullptr, *shi = nullptr, *slo = nullptr;
    __nv_bfloat16 *whi = nullptr, *wlo = nullptr;
    cudaGetSymbolAddress((void**)&gi,  g_gi);
    cudaGetSymbolAddress((void**)&xhi, g_x16hi);
    cudaGetSymbolAddress((void**)&xlo, g_x16lo);
    cudaGetSymbolAddress((void**)&shi, g_s16hi);
    cudaGetSymbolAddress((void**)&slo, g_s16lo);
    cudaGetSymbolAddress((void**)&whi, g_w16hi);
    cudaGetSymbolAddress((void**)&wlo, g_w16lo);

    cudaFuncSetAttribute(gru_persistent_kernel,
                         cudaFuncAttributeMaxDynamicSharedMemorySize,
                         RDYN_BYTES);
    cudaFuncSetAttribute(gi_gemm_bf16_kernel,
                         cudaFuncAttributeMaxDynamicSharedMemorySize,
                         GI_SMEM);

    // one-time conversions
    conv_x_kernel<<<65536, 256>>>(x, xhi, xlo);
    conv_w_kernel<<<36864, 256>>>(w_ih, whi, wlo);

    const size_t BH = (size_t)B_SZ * H_DIM;   // 65536
    dim3 ggrid(THREE_H / 128, M_ROWS / 128);  // (24, 128)

    for (int l = 0; l < L_NUM; l++) {
        const __nv_bfloat16* Ahi = (l == 0) ? xhi : shi;
        const __nv_bfloat16* Alo = (l == 0) ? xlo : slo;
        gi_gemm_bf16_kernel<<<ggrid, 256, GI_SMEM>>>(
            Ahi, Alo,
            whi + (size_t)l * THREE_H * K_DIM,
            wlo + (size_t)l * THREE_H * K_DIM,
            b_ih + (size_t)l * THREE_H,
            gi);
        gru_persistent_kernel<<<NBLK, NTHR, RDYN_BYTES>>>(
            gi,
            w_hh + (size_t)l * THREE_H * H_DIM,
            b_hh + (size_t)l * THREE_H,
            h0 + (size_t)l * BH,
            (l < L_NUM - 1) ? shi : nullptr,
            (l < L_NUM - 1) ? slo : nullptr,
            out + (size_t)l * BH);
    }
}